// round 8
// baseline (speedup 1.0000x reference)
#include <cuda_runtime.h>
#include <cstdint>
#include <string.h>
#include <math.h>

// ---------------- problem constants ----------------
#define NB    4
#define NH    6
#define NMAP  24          // NB*NH
#define SEQ   1024        // H*W
#define DH    64
#define CDIM  384
#define KTOP  734003u     // int(0.7 * 1024 * 1024)
#define SCALEF 0.125f     // 64^-0.5
#define CAND_CAP 32768

// output offsets (element counts, float32)
#define OP_OFF 0
#define AM_OFF 1572864
#define AC_OFF 1576960
#define AN_OFF 26742784
#define BM_OFF 51908608

// ---------------- scratch (device globals) ----------------
__device__ float g_q[NB * CDIM * SEQ];
__device__ float g_k[NB * CDIM * SEQ];
__device__ float g_v[NB * CDIM * SEQ];
__device__ float g_o[NB * CDIM * SEQ];
__device__ float g_attn[(size_t)NMAP * SEQ * SEQ];   // 96 MB
__device__ unsigned g_hA[NMAP * 4096];
__device__ unsigned g_hB[NMAP * 1024];
__device__ unsigned g_hC[NMAP * 1024];
__device__ unsigned g_D1[NMAP];
__device__ unsigned g_t2[NMAP];
__device__ unsigned g_D2[NMAP];
__device__ unsigned g_t3[NMAP];
__device__ unsigned g_thr[NMAP];
__device__ int g_cut[NMAP];
__device__ unsigned g_cnt[NMAP];
__device__ uint2 g_cand[NMAP * CAND_CAP];            // 6 MB
__device__ float g_part[NMAP * 64 * SEQ];

// ---------------- packed fp32x2 FMA ----------------
__device__ __forceinline__ float2 ffma2(float2 a, float2 b, float2 c)
{
    unsigned long long A, B, C, D;
    memcpy(&A, &a, 8); memcpy(&B, &b, 8); memcpy(&C, &c, 8);
    asm("fma.rn.f32x2 %0, %1, %2, %3;" : "=l"(D) : "l"(A), "l"(B), "l"(C));
    float2 r; memcpy(&r, &D, 8); return r;
}

__device__ __forceinline__ void stcs4(float* p, float4 v)
{
    asm volatile("st.global.cs.v4.f32 [%0], {%1,%2,%3,%4};"
                 :: "l"(p), "f"(v.x), "f"(v.y), "f"(v.z), "f"(v.w) : "memory");
}

// ---------------- zero small scratch ----------------
__global__ void zero_kernel()
{
    int i = blockIdx.x * 1024 + threadIdx.x;
    if (i < NMAP * 4096) g_hA[i] = 0u;
    int j = i - NMAP * 4096;
    if (j >= 0 && j < NMAP * 1024) g_hB[j] = 0u;
    int k = j - NMAP * 1024;
    if (k >= 0 && k < NMAP * 1024) g_hC[k] = 0u;
    int l = k - NMAP * 1024;
    if (l >= 0 && l < NMAP) g_cnt[l] = 0u;
}

// ---------------- QKV projection ----------------
__global__ void __launch_bounds__(256)
proj_kernel(const float* __restrict__ qin, const float* __restrict__ cin,
            const float* __restrict__ Wq, const float* __restrict__ Wk,
            const float* __restrict__ Wv)
{
    int bz = blockIdx.z;
    int b = bz / 3, p = bz - b * 3;
    const float* X = (p == 0 ? qin : cin) + b * CDIM * SEQ;
    const float* W = (p == 0 ? Wq : (p == 1 ? Wk : Wv));
    float* Y = (p == 0 ? g_q : (p == 1 ? g_k : g_v)) + b * CDIM * SEQ;

    __shared__ float As[16][132];
    __shared__ float Bs[16][132];

    int tid = threadIdx.x;
    int o0 = blockIdx.y * 128, n0 = blockIdx.x * 128;
    int ty = tid >> 4, tx = tid & 15;

    float2 acc2[8][4];
#pragma unroll
    for (int i = 0; i < 8; i++)
#pragma unroll
        for (int j = 0; j < 4; j++) acc2[i][j] = make_float2(0.f, 0.f);

    int arow = tid >> 2, acol = (tid & 3) << 2;
    int brow = tid >> 5, bcol = (tid & 31) << 2;

    for (int k0 = 0; k0 < CDIM; k0 += 16) {
#pragma unroll
        for (int r = 0; r < 2; r++) {
            float4 w4 = *(const float4*)&W[(o0 + arow + r * 64) * CDIM + k0 + acol];
            As[acol + 0][arow + r * 64] = w4.x;
            As[acol + 1][arow + r * 64] = w4.y;
            As[acol + 2][arow + r * 64] = w4.z;
            As[acol + 3][arow + r * 64] = w4.w;
        }
#pragma unroll
        for (int r = 0; r < 2; r++) {
            *(float4*)&Bs[brow + r * 8][bcol] =
                *(const float4*)&X[(k0 + brow + r * 8) * SEQ + n0 + bcol];
        }
        __syncthreads();
#pragma unroll
        for (int kk = 0; kk < 16; kk++) {
            float a[8];
            *(float4*)(a)     = *(float4*)&As[kk][ty * 8];
            *(float4*)(a + 4) = *(float4*)&As[kk][ty * 8 + 4];
            float4 b01 = *(float4*)&Bs[kk][tx * 8];
            float4 b23 = *(float4*)&Bs[kk][tx * 8 + 4];
            float2 bp[4] = { make_float2(b01.x, b01.y), make_float2(b01.z, b01.w),
                             make_float2(b23.x, b23.y), make_float2(b23.z, b23.w) };
#pragma unroll
            for (int i = 0; i < 8; i++) {
                float2 a2 = make_float2(a[i], a[i]);
#pragma unroll
                for (int pp = 0; pp < 4; pp++)
                    acc2[i][pp] = ffma2(a2, bp[pp], acc2[i][pp]);
            }
        }
        __syncthreads();
    }
#pragma unroll
    for (int i = 0; i < 8; i++) {
        int o = o0 + ty * 8 + i;
        float4 w0 = make_float4(acc2[i][0].x, acc2[i][0].y, acc2[i][1].x, acc2[i][1].y);
        float4 w1 = make_float4(acc2[i][2].x, acc2[i][2].y, acc2[i][3].x, acc2[i][3].y);
        *(float4*)&Y[o * SEQ + n0 + tx * 8]     = w0;
        *(float4*)&Y[o * SEQ + n0 + tx * 8 + 4] = w1;
    }
}

// ---------------- fused logits + softmax + 12-bit histogram ----------------
// Block: 32 query rows x all 1024 keys. Score tile lives in dynamic smem.
#define S_STRIDE 1032
#define AS_SMEM_FLOATS (32 * S_STRIDE + 64 * 36 + 16 * 132)
#define AS_SMEM_BYTES  (AS_SMEM_FLOATS * 4 + 4096 * 4)   // + hist

__global__ void __launch_bounds__(256)
attn_softhist_kernel()
{
    extern __shared__ char smraw[];
    float* Ssm = (float*)smraw;                       // [32][S_STRIDE]
    float* Qs  = Ssm + 32 * S_STRIDE;                 // [64][36]
    float* Ks  = Qs + 64 * 36;                        // [16][132]
    unsigned* hist = (unsigned*)(Ks + 16 * 132);      // [4096]

    int map = blockIdx.y;
    int b = map / NH, h = map - b * NH;
    int n0 = blockIdx.x * 32;
    const float* Q  = g_q + (b * CDIM + h * DH) * SEQ;
    const float* Kp = g_k + (b * CDIM + h * DH) * SEQ;

    int tid = threadIdx.x;
    int ty = tid >> 4, tx = tid & 15;
    int warp = tid >> 5, lane = tid & 31;

    for (int i = tid; i < 4096; i += 256) hist[i] = 0u;

    // load Q tile: 64 d x 32 n
    for (int i = tid; i < 64 * 8; i += 256) {
        int d = i >> 3, c = (i & 7) << 2;
        float4 t = *(const float4*)&Q[d * SEQ + n0 + c];
        *(float4*)&Qs[d * 36 + c] = t;
    }

    int brow = tid >> 5, bcol = (tid & 31) << 2;

    for (int m0 = 0; m0 < SEQ; m0 += 128) {
        float2 acc2[2][4];
#pragma unroll
        for (int i = 0; i < 2; i++)
#pragma unroll
            for (int j = 0; j < 4; j++) acc2[i][j] = make_float2(0.f, 0.f);

        for (int k0 = 0; k0 < DH; k0 += 16) {
            __syncthreads();
#pragma unroll
            for (int r = 0; r < 2; r++) {
                *(float4*)&Ks[(brow + r * 8) * 132 + bcol] =
                    *(const float4*)&Kp[(k0 + brow + r * 8) * SEQ + m0 + bcol];
            }
            __syncthreads();
#pragma unroll
            for (int kk = 0; kk < 16; kk++) {
                float a0 = Qs[(k0 + kk) * 36 + ty * 2];
                float a1 = Qs[(k0 + kk) * 36 + ty * 2 + 1];
                float4 b01 = *(float4*)&Ks[kk * 132 + tx * 8];
                float4 b23 = *(float4*)&Ks[kk * 132 + tx * 8 + 4];
                float2 bp[4] = { make_float2(b01.x, b01.y), make_float2(b01.z, b01.w),
                                 make_float2(b23.x, b23.y), make_float2(b23.z, b23.w) };
                float2 a20 = make_float2(a0, a0);
                float2 a21 = make_float2(a1, a1);
#pragma unroll
                for (int pp = 0; pp < 4; pp++) {
                    acc2[0][pp] = ffma2(a20, bp[pp], acc2[0][pp]);
                    acc2[1][pp] = ffma2(a21, bp[pp], acc2[1][pp]);
                }
            }
        }
        // write scaled logits to Ssm
#pragma unroll
        for (int i = 0; i < 2; i++) {
            int row = ty * 2 + i;
            float4 w0 = make_float4(acc2[i][0].x * SCALEF, acc2[i][0].y * SCALEF,
                                    acc2[i][1].x * SCALEF, acc2[i][1].y * SCALEF);
            float4 w1 = make_float4(acc2[i][2].x * SCALEF, acc2[i][2].y * SCALEF,
                                    acc2[i][3].x * SCALEF, acc2[i][3].y * SCALEF);
            *(float4*)&Ssm[row * S_STRIDE + m0 + tx * 8]     = w0;
            *(float4*)&Ssm[row * S_STRIDE + m0 + tx * 8 + 4] = w1;
        }
    }
    __syncthreads();

    // phase B: softmax per row (warp per row group of 4), same reduction order as before
    float* base = g_attn + ((size_t)map << 20);
    for (int rr = 0; rr < 4; rr++) {
        int row = warp * 4 + rr;
        float* S = Ssm + row * S_STRIDE;
        float* A = base + (size_t)(n0 + row) * SEQ;
        float4 v[8];
        float mx = -3.4e38f;
#pragma unroll
        for (int j = 0; j < 8; j++) {
            v[j] = *(float4*)&S[j * 128 + lane * 4];
            mx = fmaxf(mx, fmaxf(fmaxf(v[j].x, v[j].y), fmaxf(v[j].z, v[j].w)));
        }
#pragma unroll
        for (int o = 16; o; o >>= 1) mx = fmaxf(mx, __shfl_xor_sync(0xffffffffu, mx, o));
        float s = 0.f;
#pragma unroll
        for (int j = 0; j < 8; j++) {
            v[j].x = expf(v[j].x - mx); v[j].y = expf(v[j].y - mx);
            v[j].z = expf(v[j].z - mx); v[j].w = expf(v[j].w - mx);
            s += (v[j].x + v[j].y) + (v[j].z + v[j].w);
        }
#pragma unroll
        for (int o = 16; o; o >>= 1) s += __shfl_xor_sync(0xffffffffu, s, o);
#pragma unroll
        for (int j = 0; j < 8; j++) {
            float4 o4;
            o4.x = v[j].x / s; o4.y = v[j].y / s;
            o4.z = v[j].z / s; o4.w = v[j].w / s;
            *(float4*)&A[j * 128 + lane * 4] = o4;
            atomicAdd(&hist[__float_as_uint(o4.x) >> 20], 1u);
            atomicAdd(&hist[__float_as_uint(o4.y) >> 20], 1u);
            atomicAdd(&hist[__float_as_uint(o4.z) >> 20], 1u);
            atomicAdd(&hist[__float_as_uint(o4.w) >> 20], 1u);
        }
    }
    __syncthreads();
    for (int i = tid; i < 4096; i += 256) {
        unsigned c = hist[i];
        if (c) atomicAdd(&g_hA[map * 4096 + i], c);
    }
}

// ---------------- select digit 1 ----------------
__global__ void select1_kernel()
{
    int map = blockIdx.x, tid = threadIdx.x;
    __shared__ unsigned psum[256], ssum[256];
    __shared__ unsigned rD, rA;
    const unsigned* h = g_hA + map * 4096;
    unsigned s = 0;
    int b0 = tid * 16;
    for (int i = 0; i < 16; i++) s += h[b0 + i];
    psum[tid] = s;
    __syncthreads();
    if (tid == 0) {
        unsigned run = 0;
        for (int t = 255; t >= 0; t--) { ssum[t] = run; run += psum[t]; }
    }
    __syncthreads();
    unsigned target = KTOP;
    if (ssum[tid] < target && ssum[tid] + psum[tid] >= target) {
        unsigned acc = ssum[tid];
        for (int i = 15; i >= 0; i--) {
            unsigned c = h[b0 + i];
            if (acc + c >= target) { rD = (unsigned)(b0 + i); rA = acc; break; }
            acc += c;
        }
    }
    __syncthreads();
    if (tid == 0) { g_D1[map] = rD; g_t2[map] = target - rA; }
}

// ---------------- scan 2: hist middle 10 bits of D1-bucket ----------------
__global__ void __launch_bounds__(256)
scan2_kernel()
{
    int map = blockIdx.y, tid = threadIdx.x;
    unsigned D1 = g_D1[map];
    __shared__ unsigned hist[1024];
    for (int i = tid; i < 1024; i += 256) hist[i] = 0u;
    __syncthreads();

    const float* A = g_attn + ((size_t)map << 20);
    int fbase = blockIdx.x * 4096;
#pragma unroll 4
    for (int i = 0; i < 16; i++) {
        const float4 v = *(const float4*)&A[(size_t)(fbase + i * 256 + tid) * 4];
        unsigned k0 = __float_as_uint(v.x), k1 = __float_as_uint(v.y);
        unsigned k2 = __float_as_uint(v.z), k3 = __float_as_uint(v.w);
        if ((k0 >> 20) == D1) atomicAdd(&hist[(k0 >> 10) & 1023], 1u);
        if ((k1 >> 20) == D1) atomicAdd(&hist[(k1 >> 10) & 1023], 1u);
        if ((k2 >> 20) == D1) atomicAdd(&hist[(k2 >> 10) & 1023], 1u);
        if ((k3 >> 20) == D1) atomicAdd(&hist[(k3 >> 10) & 1023], 1u);
    }
    __syncthreads();
    for (int i = tid; i < 1024; i += 256) {
        unsigned c = hist[i];
        if (c) atomicAdd(&g_hB[map * 1024 + i], c);
    }
}

// ---------------- select digit 2 ----------------
__global__ void select2_kernel()
{
    int map = blockIdx.x, tid = threadIdx.x;   // 1024 threads
    __shared__ unsigned hist[1024];
    hist[tid] = g_hB[map * 1024 + tid];
    __syncthreads();
    if (tid == 0) {
        unsigned target = g_t2[map];
        unsigned acc = 0;
        for (int i = 1023; i >= 0; i--) {
            unsigned c = hist[i];
            if (acc + c >= target) { g_D2[map] = (unsigned)i; g_t3[map] = target - acc; break; }
            acc += c;
        }
    }
}

// ---------------- scan 3 + candidate collect (merged) ----------------
__global__ void __launch_bounds__(256)
scan3_collect_kernel()
{
    int map = blockIdx.y, tid = threadIdx.x;
    unsigned key22 = (g_D1[map] << 10) | g_D2[map];
    __shared__ unsigned hist[1024];
    for (int i = tid; i < 1024; i += 256) hist[i] = 0u;
    __syncthreads();

    const float* A = g_attn + ((size_t)map << 20);
    int fbase = blockIdx.x * 4096;
#pragma unroll 4
    for (int i = 0; i < 16; i++) {
        int fi = fbase + i * 256 + tid;
        const float4 v = *(const float4*)&A[(size_t)fi * 4];
        unsigned k[4] = { __float_as_uint(v.x), __float_as_uint(v.y),
                          __float_as_uint(v.z), __float_as_uint(v.w) };
#pragma unroll
        for (int q = 0; q < 4; q++) {
            if ((k[q] >> 10) == key22) {
                atomicAdd(&hist[k[q] & 1023], 1u);
                unsigned p = atomicAdd(&g_cnt[map], 1u);
                if (p < (unsigned)CAND_CAP)
                    g_cand[map * CAND_CAP + p] = make_uint2(k[q], (unsigned)(fi * 4 + q));
            }
        }
    }
    __syncthreads();
    for (int i = tid; i < 1024; i += 256) {
        unsigned c = hist[i];
        if (c) atomicAdd(&g_hC[map * 1024 + i], c);
    }
}

// ---------------- final: digit 3 select + tie cut from candidates ----------------
__global__ void __launch_bounds__(1024)
final3_kernel()
{
    int map = blockIdx.x, tid = threadIdx.x;
    __shared__ unsigned hist[1024];
    __shared__ unsigned sD3, sA3;
    __shared__ int eqlist[4096];
    __shared__ int eqcnt, scut;

    hist[tid] = g_hC[map * 1024 + tid];
    if (tid == 0) eqcnt = 0;
    __syncthreads();
    unsigned target = g_t3[map];
    if (tid == 0) {
        unsigned acc = 0;
        for (int i = 1023; i >= 0; i--) {
            unsigned c = hist[i];
            if (acc + c >= target) { sD3 = (unsigned)i; sA3 = acc; break; }
            acc += c;
        }
    }
    __syncthreads();
    unsigned thr = (g_D1[map] << 20) | (g_D2[map] << 10) | sD3;
    int need = (int)(target - sA3);
    int ceq = (int)hist[sD3];
    int cut;
    if (need >= ceq) {
        cut = 0x7FFFFFFF;
    } else {
        int cnt = min((int)g_cnt[map], CAND_CAP);
        const uint2* cand = g_cand + map * CAND_CAP;
        for (int i = tid; i < cnt; i += 1024) {
            uint2 e = cand[i];
            if (e.x == thr) {
                int p = atomicAdd(&eqcnt, 1);
                if (p < 4096) eqlist[p] = (int)e.y;
            }
        }
        __syncthreads();
        int c2 = min(eqcnt, 4096);
        for (int i = tid; i < c2; i += 1024) {
            int x = eqlist[i];
            int r = 0;
            for (int j = 0; j < c2; j++) r += (eqlist[j] <= x);
            if (r == need) scut = x;
        }
        __syncthreads();
        cut = scut;
    }
    if (tid == 0) { g_thr[map] = thr; g_cut[map] = cut; }
}

// ---------------- mask outputs + column sums (fused) ----------------
__global__ void __launch_bounds__(256)
maskout_colsum_kernel(float* __restrict__ out)
{
    int map = blockIdx.y, tid = threadIdx.x;
    unsigned thr = g_thr[map];
    int cut = g_cut[map];
    const float* A = g_attn + ((size_t)map << 20);
    int col = tid * 4;
    float4 sum = make_float4(0.f, 0.f, 0.f, 0.f);
    for (int r = 0; r < 16; r++) {
        int row = blockIdx.x * 16 + r;
        int im = row * SEQ + col;
        size_t e = ((size_t)map << 20) + (size_t)im;
        float4 a = *(const float4*)&A[im];
        unsigned b0 = __float_as_uint(a.x), b1 = __float_as_uint(a.y);
        unsigned b2 = __float_as_uint(a.z), b3 = __float_as_uint(a.w);
        bool s0 = (b0 > thr) || (b0 == thr && (im + 0) <= cut);
        bool s1 = (b1 > thr) || (b1 == thr && (im + 1) <= cut);
        bool s2 = (b2 > thr) || (b2 == thr && (im + 2) <= cut);
        bool s3 = (b3 > thr) || (b3 == thr && (im + 3) <= cut);
        float4 msk = make_float4(s0 ? 1.f : 0.f, s1 ? 1.f : 0.f, s2 ? 1.f : 0.f, s3 ? 1.f : 0.f);
        float4 ac  = make_float4(s0 ? a.x : 0.f, s1 ? a.y : 0.f, s2 ? a.z : 0.f, s3 ? a.w : 0.f);
        float4 an  = make_float4(s0 ? 0.f : a.x, s1 ? 0.f : a.y, s2 ? 0.f : a.z, s3 ? 0.f : a.w);
        stcs4(&out[AC_OFF + e], ac);
        stcs4(&out[AN_OFF + e], an);
        stcs4(&out[BM_OFF + e], msk);
        sum.x += a.x; sum.y += a.y; sum.z += a.z; sum.w += a.w;
    }
    *(float4*)&g_part[((map * 64 + blockIdx.x) << 10) + col] = sum;
}

__global__ void mapfinal_kernel(float* __restrict__ out)
{
    int b = blockIdx.x, tid = threadIdx.x;
    float4 acc = make_float4(0.f, 0.f, 0.f, 0.f);
    for (int j = 0; j < 384; j++) {
        float4 v = *(const float4*)&g_part[((b * 384 + j) << 10) + tid * 4];
        acc.x += v.x; acc.y += v.y; acc.z += v.z; acc.w += v.w;
    }
    const float s = 1.f / 6144.f;
    *(float4*)&out[AM_OFF + b * SEQ + tid * 4] =
        make_float4(acc.x * s, acc.y * s, acc.z * s, acc.w * s);
}

// ---------------- attn @ V ----------------
__global__ void __launch_bounds__(256)
av_kernel()
{
    int bh = blockIdx.z;
    int b = bh / NH, h = bh - b * NH;
    const float* A = g_attn + ((size_t)bh << 20);
    const float* V = g_v + (b * CDIM + h * DH) * SEQ;
    float* O = g_o + (b * CDIM + h * DH) * SEQ;
    int n0 = blockIdx.x * 128;
    int tid = threadIdx.x;

    __shared__ float Vs[32][68];
    __shared__ float Ans[32][130];

    int ty = tid >> 4, tx = tid & 15;
    float2 acc2[4][4];
#pragma unroll
    for (int i = 0; i < 4; i++)
#pragma unroll
        for (int j = 0; j < 4; j++) acc2[i][j] = make_float2(0.f, 0.f);

    int lrow = tid >> 3, lcol = (tid & 7) << 2;

    for (int m0 = 0; m0 < SEQ; m0 += 32) {
#pragma unroll
        for (int p = 0; p < 2; p++) {
            int d = lrow + p * 32;
            float4 t = *(const float4*)&V[(size_t)d * SEQ + m0 + lcol];
            Vs[lcol + 0][d] = t.x; Vs[lcol + 1][d] = t.y;
            Vs[lcol + 2][d] = t.z; Vs[lcol + 3][d] = t.w;
        }
#pragma unroll
        for (int p = 0; p < 4; p++) {
            int n = lrow + p * 32;
            float4 t = *(const float4*)&A[(size_t)(n0 + n) * SEQ + m0 + lcol];
            Ans[lcol + 0][n] = t.x; Ans[lcol + 1][n] = t.y;
            Ans[lcol + 2][n] = t.z; Ans[lcol + 3][n] = t.w;
        }
        __syncthreads();
#pragma unroll
        for (int kk = 0; kk < 32; kk++) {
            float a[4];
            *(float4*)(a) = *(float4*)&Vs[kk][ty * 4];
            float2 bp[4];
#pragma unroll
            for (int p = 0; p < 4; p++) bp[p] = *(float2*)&Ans[kk][tx * 8 + 2 * p];
#pragma unroll
            for (int i = 0; i < 4; i++) {
                float2 a2 = make_float2(a[i], a[i]);
#pragma unroll
                for (int p = 0; p < 4; p++)
                    acc2[i][p] = ffma2(a2, bp[p], acc2[i][p]);
            }
        }
        __syncthreads();
    }
#pragma unroll
    for (int i = 0; i < 4; i++) {
        int d = ty * 4 + i;
        float4 w0 = make_float4(acc2[i][0].x, acc2[i][0].y, acc2[i][1].x, acc2[i][1].y);
        float4 w1 = make_float4(acc2[i][2].x, acc2[i][2].y, acc2[i][3].x, acc2[i][3].y);
        *(float4*)&O[(size_t)d * SEQ + n0 + tx * 8]     = w0;
        *(float4*)&O[(size_t)d * SEQ + n0 + tx * 8 + 4] = w1;
    }
}

// ---------------- output projection ----------------
__global__ void __launch_bounds__(256)
oproj_kernel(const float* __restrict__ Wo, const float* __restrict__ bo,
             float* __restrict__ out)
{
    int b = blockIdx.z;
    const float* X = g_o + b * CDIM * SEQ;

    __shared__ float As[16][132];
    __shared__ float Bs[16][132];

    int tid = threadIdx.x;
    int o0 = blockIdx.y * 128, n0 = blockIdx.x * 128;
    int ty = tid >> 4, tx = tid & 15;

    float2 acc2[8][4];
#pragma unroll
    for (int i = 0; i < 8; i++)
#pragma unroll
        for (int j = 0; j < 4; j++) acc2[i][j] = make_float2(0.f, 0.f);

    int arow = tid >> 2, acol = (tid & 3) << 2;
    int brow = tid >> 5, bcol = (tid & 31) << 2;

    for (int k0 = 0; k0 < CDIM; k0 += 16) {
#pragma unroll
        for (int r = 0; r < 2; r++) {
            float4 w4 = *(const float4*)&Wo[(o0 + arow + r * 64) * CDIM + k0 + acol];
            As[acol + 0][arow + r * 64] = w4.x;
            As[acol + 1][arow + r * 64] = w4.y;
            As[acol + 2][arow + r * 64] = w4.z;
            As[acol + 3][arow + r * 64] = w4.w;
        }
#pragma unroll
        for (int r = 0; r < 2; r++) {
            *(float4*)&Bs[brow + r * 8][bcol] =
                *(const float4*)&X[(k0 + brow + r * 8) * SEQ + n0 + bcol];
        }
        __syncthreads();
#pragma unroll
        for (int kk = 0; kk < 16; kk++) {
            float a[8];
            *(float4*)(a)     = *(float4*)&As[kk][ty * 8];
            *(float4*)(a + 4) = *(float4*)&As[kk][ty * 8 + 4];
            float4 b01 = *(float4*)&Bs[kk][tx * 8];
            float4 b23 = *(float4*)&Bs[kk][tx * 8 + 4];
            float2 bp[4] = { make_float2(b01.x, b01.y), make_float2(b01.z, b01.w),
                             make_float2(b23.x, b23.y), make_float2(b23.z, b23.w) };
#pragma unroll
            for (int i = 0; i < 8; i++) {
                float2 a2 = make_float2(a[i], a[i]);
#pragma unroll
                for (int pp = 0; pp < 4; pp++)
                    acc2[i][pp] = ffma2(a2, bp[pp], acc2[i][pp]);
            }
        }
        __syncthreads();
    }
#pragma unroll
    for (int i = 0; i < 8; i++) {
        int o = o0 + ty * 8 + i;
        float bias = __ldg(&bo[o]);
        float4 w0 = make_float4(acc2[i][0].x + bias, acc2[i][0].y + bias,
                                acc2[i][1].x + bias, acc2[i][1].y + bias);
        float4 w1 = make_float4(acc2[i][2].x + bias, acc2[i][2].y + bias,
                                acc2[i][3].x + bias, acc2[i][3].y + bias);
        stcs4(&out[OP_OFF + (size_t)(b * CDIM + o) * SEQ + n0 + tx * 8], w0);
        stcs4(&out[OP_OFF + (size_t)(b * CDIM + o) * SEQ + n0 + tx * 8 + 4], w1);
    }
}

// ---------------- launch ----------------
extern "C" void kernel_launch(void* const* d_in, const int* in_sizes, int n_in,
                              void* d_out, int out_size)
{
    (void)in_sizes; (void)n_in; (void)out_size;
    const float* query   = (const float*)d_in[0];
    const float* context = (const float*)d_in[1];
    const float* Wq = (const float*)d_in[2];
    const float* Wk = (const float*)d_in[3];
    const float* Wv = (const float*)d_in[4];
    const float* Wo = (const float*)d_in[5];
    const float* bo = (const float*)d_in[6];
    float* out = (float*)d_out;

    static int smem_set = 0;
    if (!smem_set) {
        cudaFuncSetAttribute(attn_softhist_kernel,
                             cudaFuncAttributeMaxDynamicSharedMemorySize, AS_SMEM_BYTES);
        smem_set = 1;
    }

    zero_kernel<<<145, 1024>>>();
    proj_kernel<<<dim3(8, 3, 12), 256>>>(query, context, Wq, Wk, Wv);
    attn_softhist_kernel<<<dim3(32, 24), 256, AS_SMEM_BYTES>>>();
    select1_kernel<<<24, 256>>>();
    scan2_kernel<<<dim3(64, 24), 256>>>();
    select2_kernel<<<24, 1024>>>();
    scan3_collect_kernel<<<dim3(64, 24), 256>>>();
    final3_kernel<<<24, 1024>>>();
    maskout_colsum_kernel<<<dim3(64, 24), 256>>>(out);
    mapfinal_kernel<<<4, 256>>>(out);
    av_kernel<<<dim3(8, 1, 24), 256>>>();
    oproj_kernel<<<dim3(8, 3, 4), 256>>>(Wo, bo, out);
}